// round 17
// baseline (speedup 1.0000x reference)
#include <cuda_runtime.h>
#include <cuda_fp16.h>
#include <math.h>
#include <stdint.h>

#define NN 100000
#define NE 1600000
#define NE_Q (NE / 4)
#define F  128
#define SCAN_B 512
#define NBLK ((NN + SCAN_B - 1) / SCAN_B)   // 196

// Scratch (allocation-free rule: __device__ globals)
__device__ __half g_h[(size_t)NN * F];     // fp16 intermediate
__device__ __half g_agg[(size_t)NN * F];   // fp16 intermediate
__device__ __half g_w2h[F * F];            // fp16 copy of W2
__device__ int    g_cnt0[NN];              // per-quarter histograms; zero at start & end
__device__ int    g_cnt1[NN];
__device__ int    g_cnt2[NN];
__device__ int    g_cnt3[NN];
__device__ int    g_rptr[NN + 1];
__device__ int    g_end0[NN];              // placement cursors (consumed by place)
__device__ int    g_end1[NN];
__device__ int    g_end2[NN];
__device__ int    g_end3[NN];
__device__ int    g_scol[NE];
__device__ int    g_part[SCAN_B];

// Host-side fork resources (created once at load; host objects only)
static cudaStream_t g_side;
static cudaEvent_t g_ev_fork, g_ev_csr;
namespace {
struct HostInit {
  HostInit() {
    cudaStreamCreateWithFlags(&g_side, cudaStreamNonBlocking);
    cudaEventCreateWithFlags(&g_ev_fork, cudaEventDisableTiming);
    cudaEventCreateWithFlags(&g_ev_csr, cudaEventDisableTiming);
  }
};
HostInit host_init_;
}

// ================= CSR build (4-bucket split: reduced atomic contention) =================
__global__ void k_hist(const int* __restrict__ row,
                       const float* __restrict__ W2, __half* __restrict__ Wh) {
  int t = blockIdx.x * blockDim.x + threadIdx.x;
  if (t < F * F / 4) {
    float4 v = *(const float4*)(W2 + t * 4);
    *(__half2*)(Wh + t * 4)     = __floats2half2_rn(v.x, v.y);
    *(__half2*)(Wh + t * 4 + 2) = __floats2half2_rn(v.z, v.w);
  }
  int e = t * 4;
  if (e + 3 < NE) {
    int4 r = *(const int4*)(row + e);
    int q = e / NE_Q;                              // 4-packs never straddle quarters
    int* cnt = (q == 0) ? g_cnt0 : (q == 1) ? g_cnt1 : (q == 2) ? g_cnt2 : g_cnt3;
    atomicAdd(&cnt[r.x], 1);
    atomicAdd(&cnt[r.y], 1);
    atomicAdd(&cnt[r.z], 1);
    atomicAdd(&cnt[r.w], 1);
  } else {
    for (; e < NE; e++) {
      int q = e / NE_Q;
      int* cnt = (q == 0) ? g_cnt0 : (q == 1) ? g_cnt1 : (q == 2) ? g_cnt2 : g_cnt3;
      atomicAdd(&cnt[row[e]], 1);
    }
  }
}

// Block-local exclusive scan over (c0+c1+c2+c3); zeroes all; writes rptr + 4 cursors.
__global__ __launch_bounds__(SCAN_B) void k_scanA() {
  __shared__ int sh[SCAN_B];
  int g = blockIdx.x * SCAN_B + threadIdx.x;
  int v0 = 0, v1 = 0, v2 = 0, v3 = 0;
  if (g < NN) {
    v0 = g_cnt0[g]; g_cnt0[g] = 0;
    v1 = g_cnt1[g]; g_cnt1[g] = 0;
    v2 = g_cnt2[g]; g_cnt2[g] = 0;
    v3 = g_cnt3[g]; g_cnt3[g] = 0;
  }
  int v = v0 + v1 + v2 + v3;
  sh[threadIdx.x] = v;
  __syncthreads();
#pragma unroll
  for (int off = 1; off < SCAN_B; off <<= 1) {
    int t = (threadIdx.x >= off) ? sh[threadIdx.x - off] : 0;
    __syncthreads();
    sh[threadIdx.x] += t;
    __syncthreads();
  }
  if (g < NN) {
    int incl = sh[threadIdx.x];
    g_rptr[g] = incl - v;                 // exclusive (pre-offset)
    g_end3[g] = incl;
    g_end2[g] = incl - v3;
    g_end1[g] = incl - v3 - v2;
    g_end0[g] = incl - v3 - v2 - v1;      // = rptr + v0
  }
  if (threadIdx.x == SCAN_B - 1) g_part[blockIdx.x] = sh[SCAN_B - 1];
}

// Each block reduces partials below it, adds offset to rptr and all cursors.
__global__ __launch_bounds__(SCAN_B) void k_scanBC() {
  __shared__ int red[SCAN_B];
  int b = blockIdx.x;
  red[threadIdx.x] = (threadIdx.x < b && threadIdx.x < NBLK) ? g_part[threadIdx.x] : 0;
  __syncthreads();
#pragma unroll
  for (int off = SCAN_B / 2; off > 0; off >>= 1) {
    if (threadIdx.x < off) red[threadIdx.x] += red[threadIdx.x + off];
    __syncthreads();
  }
  int offset = red[0];
  int g = b * SCAN_B + threadIdx.x;
  if (g < NN) {
    g_rptr[g] += offset;
    g_end0[g] += offset;
    g_end1[g] += offset;
    g_end2[g] += offset;
    g_end3[g] += offset;
  }
  if (g == 0) g_rptr[NN] = NE;
}

// Placement: 1 edge/thread; each quarter decrements its own cursor array.
__global__ void k_place(const int* __restrict__ row, const int* __restrict__ col) {
  int e = blockIdx.x * blockDim.x + threadIdx.x;
  if (e >= NE) return;
  int r = row[e];
  int q = e / NE_Q;
  int* end = (q == 0) ? g_end0 : (q == 1) ? g_end1 : (q == 2) ? g_end2 : g_end3;
  int pos = atomicSub(&end[r], 1) - 1;
  g_scol[pos] = col[e];
}

// ================= fp16 mma.sync GEMM cores =================
#define H_STRIDE 136                        // halves per row (128 + 8 pad)
#define TILE_HALVES (128 * H_STRIDE)        // 17408 (128-row tile)
#define TILE64_HALVES (64 * H_STRIDE)       // 8704  (64-row tile)
#define GEMM_SMEM (2 * TILE_HALVES * 2)     // 69632 B (layer 1)
#define GEMM2_SMEM ((TILE64_HALVES + TILE_HALVES) * 2)  // 52224 B (layer 2)

__device__ __forceinline__ void mma_f16(float* c, const uint32_t* a, const uint32_t* b) {
  asm volatile(
      "mma.sync.aligned.m16n8k16.row.col.f32.f16.f16.f32 "
      "{%0,%1,%2,%3}, {%4,%5,%6,%7}, {%8,%9}, {%0,%1,%2,%3};"
      : "+f"(c[0]), "+f"(c[1]), "+f"(c[2]), "+f"(c[3])
      : "r"(a[0]), "r"(a[1]), "r"(a[2]), "r"(a[3]), "r"(b[0]), "r"(b[1]));
}

// ---- Layer 1: 128x128 tile, A fp32 convert-on-load (hidden behind CSR) ----
__global__ __launch_bounds__(256, 2) void k_gemm_tc(
    const float* __restrict__ A, const float* __restrict__ W,
    const float* __restrict__ bias, __half* __restrict__ C, int M) {
  extern __shared__ __half sh[];
  __half* sA = sh;
  __half* sW = sh + TILE_HALVES;
  const int tid = threadIdx.x;
  const int wid = tid >> 5;
  const int lane = tid & 31;
  const int m0 = blockIdx.x * 128;

#pragma unroll
  for (int it = 0; it < 16; it++) {
    int idx = it * 256 + tid;
    int row = idx >> 5;
    int cq = idx & 31;

    float4 va = make_float4(0.f, 0.f, 0.f, 0.f);
    if (m0 + row < M)
      va = *(const float4*)(A + (size_t)(m0 + row) * F + cq * 4);
    *(__half2*)&sA[row * H_STRIDE + cq * 4]     = __floats2half2_rn(va.x, va.y);
    *(__half2*)&sA[row * H_STRIDE + cq * 4 + 2] = __floats2half2_rn(va.z, va.w);

    float4 vw = *(const float4*)(W + (size_t)row * F + cq * 4);
    *(__half2*)&sW[row * H_STRIDE + cq * 4]     = __floats2half2_rn(vw.x, vw.y);
    *(__half2*)&sW[row * H_STRIDE + cq * 4 + 2] = __floats2half2_rn(vw.z, vw.w);
  }
  __syncthreads();

  const int wm = wid & 3, wn = wid >> 2, g = lane >> 2, t = lane & 3;
  float acc[2][8][4];
#pragma unroll
  for (int i = 0; i < 2; i++)
#pragma unroll
    for (int j = 0; j < 8; j++)
#pragma unroll
      for (int l = 0; l < 4; l++) acc[i][j][l] = 0.0f;

#pragma unroll
  for (int k16 = 0; k16 < 8; k16++) {
    const int kc = k16 * 16;
    uint32_t af[2][4];
#pragma unroll
    for (int mt = 0; mt < 2; mt++) {
      const __half* base = sA + (size_t)(wm * 32 + mt * 16 + g) * H_STRIDE + kc;
      af[mt][0] = *(const uint32_t*)(base + 2 * t);
      af[mt][1] = *(const uint32_t*)(base + 8 * H_STRIDE + 2 * t);
      af[mt][2] = *(const uint32_t*)(base + 2 * t + 8);
      af[mt][3] = *(const uint32_t*)(base + 8 * H_STRIDE + 2 * t + 8);
    }
#pragma unroll
    for (int nt = 0; nt < 8; nt++) {
      const __half* wbase = sW + (size_t)(wn * 64 + nt * 8 + g) * H_STRIDE + kc;
      uint32_t bf[2];
      bf[0] = *(const uint32_t*)(wbase + 2 * t);
      bf[1] = *(const uint32_t*)(wbase + 2 * t + 8);
#pragma unroll
      for (int mt = 0; mt < 2; mt++) mma_f16(acc[mt][nt], af[mt], bf);
    }
  }

#pragma unroll
  for (int mt = 0; mt < 2; mt++) {
    int row0 = m0 + wm * 32 + mt * 16 + g;
#pragma unroll
    for (int nt = 0; nt < 8; nt++) {
      int col = wn * 64 + nt * 8 + t * 2;
      float bx = __ldg(bias + col);
      float by = __ldg(bias + col + 1);
      if (row0 < M) {
        __half2 o = __floats2half2_rn(acc[mt][nt][0] + bx, acc[mt][nt][1] + by);
        *(__half2*)(C + (size_t)row0 * F + col) = o;
      }
      if (row0 + 8 < M) {
        __half2 o = __floats2half2_rn(acc[mt][nt][2] + bx, acc[mt][nt][3] + by);
        *(__half2*)(C + (size_t)(row0 + 8) * F + col) = o;
      }
    }
  }
}

// ---- Layer 2: 64x128 tile (higher CTA/SM), A and W fp16 via cp.async ----
// 8 warps: wm = wid&1 (two 32-row groups), wn = wid>>1 (four 32-col groups).
__global__ __launch_bounds__(256) void k_gemm_tc_h64(
    const __half* __restrict__ A, const __half* __restrict__ Wh,
    const float* __restrict__ bias, __half* __restrict__ C, int M) {
  extern __shared__ __half sh[];
  __half* sA = sh;                       // 64 x H_STRIDE
  __half* sW = sh + TILE64_HALVES;       // 128 x H_STRIDE
  const int tid = threadIdx.x;
  const int wid = tid >> 5;
  const int lane = tid & 31;
  const int m0 = blockIdx.x * 64;

  // A tile: 64 rows x 16 chunks of 16B (8 halves) = 1024; 4/thread
#pragma unroll
  for (int it = 0; it < 4; it++) {
    int idx = it * 256 + tid;
    int row = idx >> 4;
    int c8 = idx & 15;
    uint32_t dst = (uint32_t)__cvta_generic_to_shared(
        sA + (size_t)row * H_STRIDE + c8 * 8);
    const __half* src = A + (size_t)(m0 + row) * F + c8 * 8;
    int sz = (m0 + row < M) ? 16 : 0;
    asm volatile("cp.async.ca.shared.global [%0], [%1], 16, %2;"
                 :: "r"(dst), "l"(src), "r"(sz));
  }
  // W tile: 128 rows x 16 chunks of 16B = 2048; 8/thread
#pragma unroll
  for (int it = 0; it < 8; it++) {
    int idx = it * 256 + tid;
    int row = idx >> 4;
    int c8 = idx & 15;
    uint32_t dst = (uint32_t)__cvta_generic_to_shared(
        sW + (size_t)row * H_STRIDE + c8 * 8);
    asm volatile("cp.async.ca.shared.global [%0], [%1], 16;"
                 :: "r"(dst), "l"(Wh + (size_t)row * F + c8 * 8));
  }
  asm volatile("cp.async.commit_group;");

  float acc[2][4][4];
#pragma unroll
  for (int i = 0; i < 2; i++)
#pragma unroll
    for (int j = 0; j < 4; j++)
#pragma unroll
      for (int l = 0; l < 4; l++) acc[i][j][l] = 0.0f;

  const int wm = wid & 1, wn = wid >> 1, g = lane >> 2, t = lane & 3;

  asm volatile("cp.async.wait_group 0;");
  __syncthreads();

#pragma unroll
  for (int k16 = 0; k16 < 8; k16++) {
    const int kc = k16 * 16;
    uint32_t af[2][4];
#pragma unroll
    for (int mt = 0; mt < 2; mt++) {
      const __half* base = sA + (size_t)(wm * 32 + mt * 16 + g) * H_STRIDE + kc;
      af[mt][0] = *(const uint32_t*)(base + 2 * t);
      af[mt][1] = *(const uint32_t*)(base + 8 * H_STRIDE + 2 * t);
      af[mt][2] = *(const uint32_t*)(base + 2 * t + 8);
      af[mt][3] = *(const uint32_t*)(base + 8 * H_STRIDE + 2 * t + 8);
    }
#pragma unroll
    for (int nt = 0; nt < 4; nt++) {
      const __half* wbase = sW + (size_t)(wn * 32 + nt * 8 + g) * H_STRIDE + kc;
      uint32_t bf[2];
      bf[0] = *(const uint32_t*)(wbase + 2 * t);
      bf[1] = *(const uint32_t*)(wbase + 2 * t + 8);
#pragma unroll
      for (int mt = 0; mt < 2; mt++) mma_f16(acc[mt][nt], af[mt], bf);
    }
  }

#pragma unroll
  for (int mt = 0; mt < 2; mt++) {
    int row0 = m0 + wm * 32 + mt * 16 + g;
#pragma unroll
    for (int nt = 0; nt < 4; nt++) {
      int col = wn * 32 + nt * 8 + t * 2;
      float bx = __ldg(bias + col);
      float by = __ldg(bias + col + 1);
      if (row0 < M) {
        __half2 o = __floats2half2_rn(acc[mt][nt][0] + bx, acc[mt][nt][1] + by);
        *(__half2*)(C + (size_t)row0 * F + col) = o;
      }
      if (row0 + 8 < M) {
        __half2 o = __floats2half2_rn(acc[mt][nt][2] + bx, acc[mt][nt][3] + by);
        *(__half2*)(C + (size_t)(row0 + 8) * F + col) = o;
      }
    }
  }
}

// ================= CSR gather SpMM (fp16 src) + mean =================
__device__ __forceinline__ void acc_edge(float4& acc, const __half* src, int c, int lane) {
  uint2 v = ((const uint2*)(src + (size_t)c * F))[lane];
  float2 f0 = __half22float2(*(__half2*)&v.x);
  float2 f1 = __half22float2(*(__half2*)&v.y);
  acc.x += f0.x; acc.y += f0.y; acc.z += f1.x; acc.w += f1.y;
}

// MODE 0: ELU + fp16 out. MODE 1: no ELU + fp32 out.
template <int MODE>
__global__ __launch_bounds__(256) void k_gather(
    const __half* __restrict__ src, void* __restrict__ dst_) {
  int node = blockIdx.x * 8 + (threadIdx.x >> 5);
  if (node >= NN) return;
  int lane = threadIdx.x & 31;

  int s = g_rptr[node];
  int e = g_rptr[node + 1];

  float4 acc = make_float4(0.f, 0.f, 0.f, 0.f);
  int j = s;
  for (; j + 4 <= e; j += 4) {
    int c0 = __ldg(&g_scol[j + 0]);
    int c1 = __ldg(&g_scol[j + 1]);
    int c2 = __ldg(&g_scol[j + 2]);
    int c3 = __ldg(&g_scol[j + 3]);
    acc_edge(acc, src, c0, lane);
    acc_edge(acc, src, c1, lane);
    acc_edge(acc, src, c2, lane);
    acc_edge(acc, src, c3, lane);
  }
  for (; j < e; j++) acc_edge(acc, src, __ldg(&g_scol[j]), lane);

  float inv = (e > s) ? 1.0f / (float)(e - s) : 0.0f;
  acc.x *= inv; acc.y *= inv; acc.z *= inv; acc.w *= inv;
  if (MODE == 0) {
    acc.x = acc.x > 0.f ? acc.x : expm1f(acc.x);
    acc.y = acc.y > 0.f ? acc.y : expm1f(acc.y);
    acc.z = acc.z > 0.f ? acc.z : expm1f(acc.z);
    acc.w = acc.w > 0.f ? acc.w : expm1f(acc.w);
    __half* dst = (__half*)dst_;
    uint2 o;
    *(__half2*)&o.x = __floats2half2_rn(acc.x, acc.y);
    *(__half2*)&o.y = __floats2half2_rn(acc.z, acc.w);
    ((uint2*)(dst + (size_t)node * F))[lane] = o;
  } else {
    float* dst = (float*)dst_;
    ((float4*)(dst + (size_t)node * F))[lane] = acc;
  }
}

extern "C" void kernel_launch(void* const* d_in, const int* in_sizes, int n_in,
                              void* d_out, int out_size) {
  const float* x  = (const float*)d_in[0];
  const int*   ei = (const int*)d_in[1];
  const float* W1 = (const float*)d_in[2];
  const float* b1 = (const float*)d_in[3];
  const float* W2 = (const float*)d_in[4];
  const float* b2 = (const float*)d_in[5];
  const int* row = ei;
  const int* col = ei + NE;
  float* out = (float*)d_out;

  void* p_h = nullptr;
  void* p_agg = nullptr;
  void* p_w2h = nullptr;
  cudaGetSymbolAddress(&p_h, g_h);
  cudaGetSymbolAddress(&p_agg, g_agg);
  cudaGetSymbolAddress(&p_w2h, g_w2h);
  __half* h   = (__half*)p_h;
  __half* agg = (__half*)p_agg;
  __half* w2h = (__half*)p_w2h;

  cudaFuncSetAttribute(k_gemm_tc, cudaFuncAttributeMaxDynamicSharedMemorySize, GEMM_SMEM);
  cudaFuncSetAttribute(k_gemm_tc_h64, cudaFuncAttributeMaxDynamicSharedMemorySize, GEMM2_SMEM);

  const int gblocks = (NN + 127) / 128;       // 782
  const int g64blocks = (NN + 63) / 64;       // 1563
  const int eblocks1 = (NE + 511) / 512;      // 3125
  const int eblocks4 = (NE / 4 + 511) / 512;  // 782

  // ---- fork: CSR build (+W2 convert) on side stream, GEMM1 on main ----
  cudaEventRecord(g_ev_fork, 0);
  cudaStreamWaitEvent(g_side, g_ev_fork, 0);

  k_hist<<<eblocks4, 512, 0, g_side>>>(row, W2, w2h);
  k_scanA<<<NBLK, SCAN_B, 0, g_side>>>();
  k_scanBC<<<NBLK, SCAN_B, 0, g_side>>>();
  k_place<<<eblocks1, 512, 0, g_side>>>(row, col);
  cudaEventRecord(g_ev_csr, g_side);

  k_gemm_tc<<<gblocks, 256, GEMM_SMEM>>>(x, W1, b1, h, NN);        // h = x W1^T + b1

  // ---- join, then the dependent chain ----
  cudaStreamWaitEvent(0, g_ev_csr, 0);
  k_gather<0><<<(NN + 7) / 8, 256>>>(h, agg);                      // agg = elu(mean(h)) [fp16]
  k_gemm_tc_h64<<<g64blocks, 256, GEMM2_SMEM>>>(agg, w2h, b2, h, NN); // h = agg W2h^T + b2
  k_gather<1><<<(NN + 7) / 8, 256>>>(h, out);                      // out = mean(h) [fp32]
}